// round 1
// baseline (speedup 1.0000x reference)
#include <cuda_runtime.h>

#define NN 50000
#define NE 1600000
#define D  128
#define OD 64
#define NL 3

// ---------------- device scratch (allowed: __device__ globals) ----------------
__device__ float g_h[NN * D];      // current node features
__device__ float g_x[NN * D];      // MLP hidden (pre-BN)
__device__ float g_agg[NN * D];    // neighbor sums
__device__ float g_stats[2 * D];   // per-channel sum, sumsq
__device__ float g_bnp[2 * D];     // per-channel scale, shift

// ---------------- init / zero ----------------
__global__ void copy_h_kernel(const float* __restrict__ nf) {
    size_t i = (size_t)blockIdx.x * blockDim.x + threadIdx.x;
    size_t n4 = (size_t)NN * D / 4;
    const float4* src = (const float4*)nf;
    float4* dstp = (float4*)g_h;
    for (; i < n4; i += (size_t)gridDim.x * blockDim.x) dstp[i] = src[i];
}

__global__ void zero_agg_kernel() {
    size_t i = (size_t)blockIdx.x * blockDim.x + threadIdx.x;
    size_t n4 = (size_t)NN * D / 4;
    float4 z = make_float4(0.f, 0.f, 0.f, 0.f);
    float4* p = (float4*)g_agg;
    for (; i < n4; i += (size_t)gridDim.x * blockDim.x) p[i] = z;
    if (blockIdx.x == 0 && threadIdx.x < 2 * D) g_stats[threadIdx.x] = 0.f;
}

// ---------------- edge scatter: one warp per edge, red.v4 ----------------
__global__ void __launch_bounds__(256) scatter_kernel(const int* __restrict__ src,
                                                      const int* __restrict__ dst) {
    int e = blockIdx.x * 8 + (threadIdx.x >> 5);
    if (e >= NE) return;
    int lane = threadIdx.x & 31;
    int s = __ldg(src + e);
    int d = __ldg(dst + e);
    const float4 v = *(const float4*)(g_h + (size_t)s * D + lane * 4);
    float* p = g_agg + (size_t)d * D + lane * 4;
    asm volatile("red.global.add.v4.f32 [%0], {%1,%2,%3,%4};"
                 :: "l"(p), "f"(v.x), "f"(v.y), "f"(v.z), "f"(v.w)
                 : "memory");
}

// ---------------- GEMM1: x = ((1+eps)h + agg) @ W1 + b1, + BN stats ----------------
// BM=64, BN=128, BK=16, 256 threads, 8x4 per-thread tile.
__global__ void __launch_bounds__(256) gemm1_kernel(const float* __restrict__ W1,
                                                    const float* __restrict__ b1,
                                                    const float* __restrict__ eps,
                                                    int layer) {
    __shared__ float Bs[16][128];
    __shared__ float As[16][68];
    __shared__ float Red[2][8][128];

    int tid = threadIdx.x;
    int tn = tid & 31;       // col group: n0 = tn*4
    int tm = tid >> 5;       // row group: rows tm*8 .. tm*8+7
    int m0 = blockIdx.x * 64;
    const float* W = W1 + (size_t)layer * D * D;
    float oe = 1.0f + __ldg(eps + layer);

    float acc[8][4];
#pragma unroll
    for (int r = 0; r < 8; r++)
#pragma unroll
        for (int c = 0; c < 4; c++) acc[r][c] = 0.f;

    int lm = tid >> 2;            // 0..63 : row within tile for A loads
    int lk = (tid & 3) * 4;       // 0,4,8,12 : k offset within chunk
    int gm_ld = m0 + lm;

    for (int kk = 0; kk < D; kk += 16) {
        // load B chunk (16x128 = 512 float4, 2 per thread)
        {
            const float4* Wv = (const float4*)(W + kk * D);
            float4* Bv = (float4*)&Bs[0][0];
            Bv[tid] = Wv[tid];
            Bv[tid + 256] = Wv[tid + 256];
        }
        // load A chunk fused: (1+eps)*h + agg, transposed into As[k][m]
        {
            float4 a = make_float4(0.f, 0.f, 0.f, 0.f);
            if (gm_ld < NN) {
                const float4 hv = *(const float4*)(g_h + (size_t)gm_ld * D + kk + lk);
                const float4 av = *(const float4*)(g_agg + (size_t)gm_ld * D + kk + lk);
                a.x = fmaf(oe, hv.x, av.x);
                a.y = fmaf(oe, hv.y, av.y);
                a.z = fmaf(oe, hv.z, av.z);
                a.w = fmaf(oe, hv.w, av.w);
            }
            As[lk + 0][lm] = a.x;
            As[lk + 1][lm] = a.y;
            As[lk + 2][lm] = a.z;
            As[lk + 3][lm] = a.w;
        }
        __syncthreads();
#pragma unroll
        for (int k = 0; k < 16; k++) {
            float4 b = *(const float4*)(&Bs[k][tn * 4]);
            float4 a0 = *(const float4*)(&As[k][tm * 8]);
            float4 a1 = *(const float4*)(&As[k][tm * 8 + 4]);
            float av[8] = {a0.x, a0.y, a0.z, a0.w, a1.x, a1.y, a1.z, a1.w};
#pragma unroll
            for (int r = 0; r < 8; r++) {
                acc[r][0] = fmaf(av[r], b.x, acc[r][0]);
                acc[r][1] = fmaf(av[r], b.y, acc[r][1]);
                acc[r][2] = fmaf(av[r], b.z, acc[r][2]);
                acc[r][3] = fmaf(av[r], b.w, acc[r][3]);
            }
        }
        __syncthreads();
    }

    // epilogue: add bias, store x, accumulate BN partial stats
    float4 bb = *(const float4*)(b1 + (size_t)layer * D + tn * 4);
    float s[4] = {0.f, 0.f, 0.f, 0.f}, q[4] = {0.f, 0.f, 0.f, 0.f};
#pragma unroll
    for (int r = 0; r < 8; r++) {
        int gm = m0 + tm * 8 + r;
        if (gm < NN) {
            float4 v;
            v.x = acc[r][0] + bb.x;
            v.y = acc[r][1] + bb.y;
            v.z = acc[r][2] + bb.z;
            v.w = acc[r][3] + bb.w;
            *(float4*)(g_x + (size_t)gm * D + tn * 4) = v;
            s[0] += v.x; s[1] += v.y; s[2] += v.z; s[3] += v.w;
            q[0] += v.x * v.x; q[1] += v.y * v.y;
            q[2] += v.z * v.z; q[3] += v.w * v.w;
        }
    }
#pragma unroll
    for (int c = 0; c < 4; c++) {
        Red[0][tm][tn * 4 + c] = s[c];
        Red[1][tm][tn * 4 + c] = q[c];
    }
    __syncthreads();
    if (tm < 2) {
#pragma unroll
        for (int c = 0; c < 4; c++) {
            float t = 0.f;
#pragma unroll
            for (int r = 0; r < 8; r++) t += Red[tm][r][tn * 4 + c];
            atomicAdd(&g_stats[tm * D + tn * 4 + c], t);
        }
    }
}

// ---------------- BN finalize: scale/shift ----------------
__global__ void bnfin_kernel(const float* __restrict__ gamma,
                             const float* __restrict__ beta, int layer) {
    int n = threadIdx.x;  // 128 threads
    float inv = 1.0f / (float)NN;
    float mu = g_stats[n] * inv;
    float var = g_stats[D + n] * inv - mu * mu;
    float rs = rsqrtf(var + 1e-5f);
    float sc = rs * __ldg(gamma + (size_t)layer * D + n);
    g_bnp[n] = sc;
    g_bnp[D + n] = __ldg(beta + (size_t)layer * D + n) - mu * sc;
}

// ---------------- GEMM2: h = relu( relu(BN(x)) @ W2 + b2 ) ----------------
__global__ void __launch_bounds__(256) gemm2_kernel(const float* __restrict__ W2,
                                                    const float* __restrict__ b2,
                                                    int layer) {
    __shared__ float Bs[16][128];
    __shared__ float As[16][68];

    int tid = threadIdx.x;
    int tn = tid & 31;
    int tm = tid >> 5;
    int m0 = blockIdx.x * 64;
    const float* W = W2 + (size_t)layer * D * D;

    float acc[8][4];
#pragma unroll
    for (int r = 0; r < 8; r++)
#pragma unroll
        for (int c = 0; c < 4; c++) acc[r][c] = 0.f;

    int lm = tid >> 2;
    int lk = (tid & 3) * 4;
    int gm_ld = m0 + lm;

    for (int kk = 0; kk < D; kk += 16) {
        {
            const float4* Wv = (const float4*)(W + kk * D);
            float4* Bv = (float4*)&Bs[0][0];
            Bv[tid] = Wv[tid];
            Bv[tid + 256] = Wv[tid + 256];
        }
        {
            float4 a = make_float4(0.f, 0.f, 0.f, 0.f);
            if (gm_ld < NN) {
                const float4 xv = *(const float4*)(g_x + (size_t)gm_ld * D + kk + lk);
                const float4 sc = *(const float4*)(g_bnp + kk + lk);
                const float4 sh = *(const float4*)(g_bnp + D + kk + lk);
                a.x = fmaxf(fmaf(xv.x, sc.x, sh.x), 0.f);
                a.y = fmaxf(fmaf(xv.y, sc.y, sh.y), 0.f);
                a.z = fmaxf(fmaf(xv.z, sc.z, sh.z), 0.f);
                a.w = fmaxf(fmaf(xv.w, sc.w, sh.w), 0.f);
            }
            As[lk + 0][lm] = a.x;
            As[lk + 1][lm] = a.y;
            As[lk + 2][lm] = a.z;
            As[lk + 3][lm] = a.w;
        }
        __syncthreads();
#pragma unroll
        for (int k = 0; k < 16; k++) {
            float4 b = *(const float4*)(&Bs[k][tn * 4]);
            float4 a0 = *(const float4*)(&As[k][tm * 8]);
            float4 a1 = *(const float4*)(&As[k][tm * 8 + 4]);
            float av[8] = {a0.x, a0.y, a0.z, a0.w, a1.x, a1.y, a1.z, a1.w};
#pragma unroll
            for (int r = 0; r < 8; r++) {
                acc[r][0] = fmaf(av[r], b.x, acc[r][0]);
                acc[r][1] = fmaf(av[r], b.y, acc[r][1]);
                acc[r][2] = fmaf(av[r], b.z, acc[r][2]);
                acc[r][3] = fmaf(av[r], b.w, acc[r][3]);
            }
        }
        __syncthreads();
    }

    float4 bb = *(const float4*)(b2 + (size_t)layer * D + tn * 4);
#pragma unroll
    for (int r = 0; r < 8; r++) {
        int gm = m0 + tm * 8 + r;
        if (gm < NN) {
            float4 v;
            v.x = fmaxf(acc[r][0] + bb.x, 0.f);
            v.y = fmaxf(acc[r][1] + bb.y, 0.f);
            v.z = fmaxf(acc[r][2] + bb.z, 0.f);
            v.w = fmaxf(acc[r][3] + bb.w, 0.f);
            *(float4*)(g_h + (size_t)gm * D + tn * 4) = v;
        }
    }
}

// ---------------- GEMM3 (final): out = h @ Wout + bout ----------------
// BM=64, BN=64, BK=16, 256 threads, 4x4 per-thread tile.
__global__ void __launch_bounds__(256) gemm3_kernel(const float* __restrict__ Wout,
                                                    const float* __restrict__ bout,
                                                    float* __restrict__ out) {
    __shared__ float Bs[16][64];
    __shared__ float As[16][68];

    int tid = threadIdx.x;
    int tn = tid & 15;   // cols: n0 = tn*4 (0..60)
    int tm = tid >> 4;   // rows: tm*4 .. tm*4+3 (tm 0..15)
    int m0 = blockIdx.x * 64;

    float acc[4][4];
#pragma unroll
    for (int r = 0; r < 4; r++)
#pragma unroll
        for (int c = 0; c < 4; c++) acc[r][c] = 0.f;

    int lm = tid >> 2;
    int lk = (tid & 3) * 4;
    int gm_ld = m0 + lm;

    for (int kk = 0; kk < D; kk += 16) {
        {
            const float4* Wv = (const float4*)(Wout + kk * OD);
            float4* Bv = (float4*)&Bs[0][0];
            Bv[tid] = Wv[tid];  // 16*64/4 = 256 float4
        }
        {
            float4 a = make_float4(0.f, 0.f, 0.f, 0.f);
            if (gm_ld < NN) {
                a = *(const float4*)(g_h + (size_t)gm_ld * D + kk + lk);
            }
            As[lk + 0][lm] = a.x;
            As[lk + 1][lm] = a.y;
            As[lk + 2][lm] = a.z;
            As[lk + 3][lm] = a.w;
        }
        __syncthreads();
#pragma unroll
        for (int k = 0; k < 16; k++) {
            float4 b = *(const float4*)(&Bs[k][tn * 4]);
            float4 a = *(const float4*)(&As[k][tm * 4]);
            float av[4] = {a.x, a.y, a.z, a.w};
#pragma unroll
            for (int r = 0; r < 4; r++) {
                acc[r][0] = fmaf(av[r], b.x, acc[r][0]);
                acc[r][1] = fmaf(av[r], b.y, acc[r][1]);
                acc[r][2] = fmaf(av[r], b.z, acc[r][2]);
                acc[r][3] = fmaf(av[r], b.w, acc[r][3]);
            }
        }
        __syncthreads();
    }

    float4 bb = *(const float4*)(bout + tn * 4);
#pragma unroll
    for (int r = 0; r < 4; r++) {
        int gm = m0 + tm * 4 + r;
        if (gm < NN) {
            float4 v;
            v.x = acc[r][0] + bb.x;
            v.y = acc[r][1] + bb.y;
            v.z = acc[r][2] + bb.z;
            v.w = acc[r][3] + bb.w;
            *(float4*)(out + (size_t)gm * OD + tn * 4) = v;
        }
    }
}

// ---------------- launch ----------------
extern "C" void kernel_launch(void* const* d_in, const int* in_sizes, int n_in,
                              void* d_out, int out_size) {
    const float* node_feat = (const float*)d_in[0];
    const int*   src       = (const int*)d_in[1];
    const int*   dst       = (const int*)d_in[2];
    const float* W1        = (const float*)d_in[3];
    const float* b1        = (const float*)d_in[4];
    const float* gamma     = (const float*)d_in[5];
    const float* beta      = (const float*)d_in[6];
    const float* W2        = (const float*)d_in[7];
    const float* b2        = (const float*)d_in[8];
    const float* eps       = (const float*)d_in[9];
    const float* Wout      = (const float*)d_in[10];
    const float* bout      = (const float*)d_in[11];
    float* out = (float*)d_out;

    const int gemm_grid = (NN + 63) / 64;        // 782
    const int scat_grid = (NE + 7) / 8;          // 200000

    copy_h_kernel<<<2048, 256>>>(node_feat);
    for (int l = 0; l < NL; l++) {
        zero_agg_kernel<<<2048, 256>>>();
        scatter_kernel<<<scat_grid, 256>>>(src, dst);
        gemm1_kernel<<<gemm_grid, 256>>>(W1, b1, eps, l);
        bnfin_kernel<<<1, 128>>>(gamma, beta, l);
        gemm2_kernel<<<gemm_grid, 256>>>(W2, b2, l);
    }
    gemm3_kernel<<<gemm_grid, 256>>>(Wout, bout, out);
}

// round 3
// speedup vs baseline: 1.4456x; 1.4456x over previous
#include <cuda_runtime.h>

#define NN 50000
#define NE 1600000
#define D  128
#define OD 64
#define NL 3

// ---------------- device scratch ----------------
__device__ float g_h[NN * D];      // node features (output of each layer)
__device__ float g_x[NN * D];      // MLP hidden (pre-BN)
__device__ float g_xin[NN * D];    // (1+eps)*h + agg   (GEMM1 input)
__device__ float g_stats[2 * D];   // per-channel sum, sumsq
__device__ float g_bnp[2 * D];     // per-channel scale, shift

// CSR (built per call, reused across 3 layers)
__device__ int g_cnt[NN];
__device__ int g_cur[NN];
__device__ int g_off[NN + 1];
__device__ int g_csrc[NE];

// ---------------- CSR build ----------------
__global__ void csr_zero_kernel() {
    int i = blockIdx.x * blockDim.x + threadIdx.x;
    if (i < NN) g_cnt[i] = 0;
    if (i == 0) g_off[0] = 0;
}

__global__ void csr_hist_kernel(const int* __restrict__ dst) {
    int e = blockIdx.x * blockDim.x + threadIdx.x;   // grid sized exactly NE
    atomicAdd(&g_cnt[__ldg(dst + e)], 1);
}

__global__ void csr_scan_kernel() {
    __shared__ int sh[1024];
    __shared__ int sbase;
    int tid = threadIdx.x;
    if (tid == 0) sbase = 0;
    __syncthreads();
    for (int chunk = 0; chunk < NN; chunk += 1024) {
        int i = chunk + tid;
        int v = (i < NN) ? g_cnt[i] : 0;
        sh[tid] = v;
        __syncthreads();
#pragma unroll
        for (int off = 1; off < 1024; off <<= 1) {
            int t = (tid >= off) ? sh[tid - off] : 0;
            __syncthreads();
            sh[tid] += t;
            __syncthreads();
        }
        int incl = sh[tid];
        int base = sbase;
        __syncthreads();
        if (tid == 1023) sbase = base + incl;
        if (i < NN) {
            g_off[i + 1] = base + incl;
            g_cur[i]     = base + incl - v;
        }
        __syncthreads();
    }
}

__global__ void csr_fill_kernel(const int* __restrict__ src,
                                const int* __restrict__ dst) {
    int e = blockIdx.x * blockDim.x + threadIdx.x;
    int d = __ldg(dst + e);
    int p = atomicAdd(&g_cur[d], 1);
    g_csrc[p] = __ldg(src + e);
}

// ---------------- gather: xin[d] = (1+eps)*h[d] + sum_{s in N(d)} h[s] ----------------
// h pointer is resolved IN DEVICE CODE (g_h symbol address is only valid there).
__global__ void __launch_bounds__(256) gather_kernel(const float* __restrict__ nf,
                                                     const float* __restrict__ eps,
                                                     int layer) {
    if (blockIdx.x == 0 && threadIdx.x < 2 * D) g_stats[threadIdx.x] = 0.f;

    const float* __restrict__ h = (layer == 0) ? nf : (const float*)g_h;

    int node = blockIdx.x * 8 + (threadIdx.x >> 5);
    if (node >= NN) return;
    int lane = threadIdx.x & 31;
    float oe = 1.0f + __ldg(eps + layer);

    int beg = g_off[node];
    int end = g_off[node + 1];

    const float4 hv = *(const float4*)(h + (size_t)node * D + lane * 4);
    float4 acc;
    acc.x = oe * hv.x; acc.y = oe * hv.y; acc.z = oe * hv.z; acc.w = oe * hv.w;

    int i = beg;
    for (; i + 3 < end; i += 4) {
        int s0 = __ldg(g_csrc + i);
        int s1 = __ldg(g_csrc + i + 1);
        int s2 = __ldg(g_csrc + i + 2);
        int s3 = __ldg(g_csrc + i + 3);
        float4 v0 = *(const float4*)(h + (size_t)s0 * D + lane * 4);
        float4 v1 = *(const float4*)(h + (size_t)s1 * D + lane * 4);
        float4 v2 = *(const float4*)(h + (size_t)s2 * D + lane * 4);
        float4 v3 = *(const float4*)(h + (size_t)s3 * D + lane * 4);
        acc.x += v0.x + v1.x + v2.x + v3.x;
        acc.y += v0.y + v1.y + v2.y + v3.y;
        acc.z += v0.z + v1.z + v2.z + v3.z;
        acc.w += v0.w + v1.w + v2.w + v3.w;
    }
    for (; i < end; i++) {
        int s = __ldg(g_csrc + i);
        float4 v = *(const float4*)(h + (size_t)s * D + lane * 4);
        acc.x += v.x; acc.y += v.y; acc.z += v.z; acc.w += v.w;
    }
    *(float4*)(g_xin + (size_t)node * D + lane * 4) = acc;
}

// ---------------- GEMM1 (pipelined): x = xin @ W1 + b1, + BN stats ----------------
// BM=64, BN=128, BK=16, 256 threads, 8x4 per-thread tile, double-buffered smem.
__global__ void __launch_bounds__(256) gemm1_kernel(const float* __restrict__ W1,
                                                    const float* __restrict__ b1,
                                                    int layer) {
    __shared__ float Bs[2][16][128];
    __shared__ float As[2][16][68];

    int tid = threadIdx.x;
    int tn = tid & 31;
    int tm = tid >> 5;
    int m0 = blockIdx.x * 64;
    const float* W = W1 + (size_t)layer * D * D;

    float acc[8][4];
#pragma unroll
    for (int r = 0; r < 8; r++)
#pragma unroll
        for (int c = 0; c < 4; c++) acc[r][c] = 0.f;

    int lm = tid >> 2;
    int lk = (tid & 3) * 4;
    int gm_ld = m0 + lm;

    // prologue: chunk 0
    {
        float4 a = make_float4(0.f, 0.f, 0.f, 0.f);
        if (gm_ld < NN) a = *(const float4*)(g_xin + (size_t)gm_ld * D + lk);
        const float4* Wv = (const float4*)W;
        float4 b0 = Wv[tid], b1v = Wv[tid + 256];
        As[0][lk + 0][lm] = a.x; As[0][lk + 1][lm] = a.y;
        As[0][lk + 2][lm] = a.z; As[0][lk + 3][lm] = a.w;
        float4* Bv = (float4*)&Bs[0][0][0];
        Bv[tid] = b0; Bv[tid + 256] = b1v;
    }
    __syncthreads();

#pragma unroll
    for (int kk = 0; kk < 8; kk++) {
        const int cur = kk & 1;
        float4 na, nb0, nb1;
        if (kk < 7) {
            int kc = (kk + 1) * 16;
            na = make_float4(0.f, 0.f, 0.f, 0.f);
            if (gm_ld < NN) na = *(const float4*)(g_xin + (size_t)gm_ld * D + kc + lk);
            const float4* Wv = (const float4*)(W + kc * D);
            nb0 = Wv[tid]; nb1 = Wv[tid + 256];
        }
#pragma unroll
        for (int k = 0; k < 16; k++) {
            float4 b = *(const float4*)(&Bs[cur][k][tn * 4]);
            float4 a0 = *(const float4*)(&As[cur][k][tm * 8]);
            float4 a1 = *(const float4*)(&As[cur][k][tm * 8 + 4]);
            float av[8] = {a0.x, a0.y, a0.z, a0.w, a1.x, a1.y, a1.z, a1.w};
#pragma unroll
            for (int r = 0; r < 8; r++) {
                acc[r][0] = fmaf(av[r], b.x, acc[r][0]);
                acc[r][1] = fmaf(av[r], b.y, acc[r][1]);
                acc[r][2] = fmaf(av[r], b.z, acc[r][2]);
                acc[r][3] = fmaf(av[r], b.w, acc[r][3]);
            }
        }
        if (kk < 7) {
            const int nxt = cur ^ 1;
            As[nxt][lk + 0][lm] = na.x; As[nxt][lk + 1][lm] = na.y;
            As[nxt][lk + 2][lm] = na.z; As[nxt][lk + 3][lm] = na.w;
            float4* Bv = (float4*)&Bs[nxt][0][0];
            Bv[tid] = nb0; Bv[tid + 256] = nb1;
            __syncthreads();
        }
    }

    // epilogue: bias, store x, BN partial stats (reuse Bs[0] as reduction buffer)
    float4 bb = *(const float4*)(b1 + (size_t)layer * D + tn * 4);
    float s[4] = {0.f, 0.f, 0.f, 0.f}, q[4] = {0.f, 0.f, 0.f, 0.f};
#pragma unroll
    for (int r = 0; r < 8; r++) {
        int gm = m0 + tm * 8 + r;
        if (gm < NN) {
            float4 v;
            v.x = acc[r][0] + bb.x;
            v.y = acc[r][1] + bb.y;
            v.z = acc[r][2] + bb.z;
            v.w = acc[r][3] + bb.w;
            *(float4*)(g_x + (size_t)gm * D + tn * 4) = v;
            s[0] += v.x; s[1] += v.y; s[2] += v.z; s[3] += v.w;
            q[0] += v.x * v.x; q[1] += v.y * v.y;
            q[2] += v.z * v.z; q[3] += v.w * v.w;
        }
    }
    __syncthreads();
    float* Red = &Bs[0][0][0];  // reused as [2][8][128]
#pragma unroll
    for (int c = 0; c < 4; c++) {
        Red[(0 * 8 + tm) * 128 + tn * 4 + c] = s[c];
        Red[(1 * 8 + tm) * 128 + tn * 4 + c] = q[c];
    }
    __syncthreads();
    if (tm < 2) {
#pragma unroll
        for (int c = 0; c < 4; c++) {
            float t = 0.f;
#pragma unroll
            for (int r = 0; r < 8; r++) t += Red[(tm * 8 + r) * 128 + tn * 4 + c];
            atomicAdd(&g_stats[tm * D + tn * 4 + c], t);
        }
    }
}

// ---------------- BN finalize ----------------
__global__ void bnfin_kernel(const float* __restrict__ gamma,
                             const float* __restrict__ beta, int layer) {
    int n = threadIdx.x;  // 128 threads
    float inv = 1.0f / (float)NN;
    float mu = g_stats[n] * inv;
    float var = g_stats[D + n] * inv - mu * mu;
    float rs = rsqrtf(var + 1e-5f);
    float sc = rs * __ldg(gamma + (size_t)layer * D + n);
    g_bnp[n] = sc;
    g_bnp[D + n] = __ldg(beta + (size_t)layer * D + n) - mu * sc;
}

// ---------------- GEMM2 (pipelined): h = relu( relu(BN(x)) @ W2 + b2 ) ----------------
__global__ void __launch_bounds__(256) gemm2_kernel(const float* __restrict__ W2,
                                                    const float* __restrict__ b2,
                                                    int layer) {
    __shared__ float Bs[2][16][128];
    __shared__ float As[2][16][68];

    int tid = threadIdx.x;
    int tn = tid & 31;
    int tm = tid >> 5;
    int m0 = blockIdx.x * 64;
    const float* W = W2 + (size_t)layer * D * D;

    float acc[8][4];
#pragma unroll
    for (int r = 0; r < 8; r++)
#pragma unroll
        for (int c = 0; c < 4; c++) acc[r][c] = 0.f;

    int lm = tid >> 2;
    int lk = (tid & 3) * 4;
    int gm_ld = m0 + lm;

    // prologue: chunk 0 with BN+ReLU applied to A
    {
        float4 a = make_float4(0.f, 0.f, 0.f, 0.f);
        if (gm_ld < NN) {
            const float4 xv = *(const float4*)(g_x + (size_t)gm_ld * D + lk);
            const float4 sc = *(const float4*)(g_bnp + lk);
            const float4 sh = *(const float4*)(g_bnp + D + lk);
            a.x = fmaxf(fmaf(xv.x, sc.x, sh.x), 0.f);
            a.y = fmaxf(fmaf(xv.y, sc.y, sh.y), 0.f);
            a.z = fmaxf(fmaf(xv.z, sc.z, sh.z), 0.f);
            a.w = fmaxf(fmaf(xv.w, sc.w, sh.w), 0.f);
        }
        const float4* Wv = (const float4*)W;
        float4 b0 = Wv[tid], b1v = Wv[tid + 256];
        As[0][lk + 0][lm] = a.x; As[0][lk + 1][lm] = a.y;
        As[0][lk + 2][lm] = a.z; As[0][lk + 3][lm] = a.w;
        float4* Bv = (float4*)&Bs[0][0][0];
        Bv[tid] = b0; Bv[tid + 256] = b1v;
    }
    __syncthreads();

#pragma unroll
    for (int kk = 0; kk < 8; kk++) {
        const int cur = kk & 1;
        float4 na, nb0, nb1;
        if (kk < 7) {
            int kc = (kk + 1) * 16;
            na = make_float4(0.f, 0.f, 0.f, 0.f);
            if (gm_ld < NN) {
                const float4 xv = *(const float4*)(g_x + (size_t)gm_ld * D + kc + lk);
                const float4 sc = *(const float4*)(g_bnp + kc + lk);
                const float4 sh = *(const float4*)(g_bnp + D + kc + lk);
                na.x = fmaxf(fmaf(xv.x, sc.x, sh.x), 0.f);
                na.y = fmaxf(fmaf(xv.y, sc.y, sh.y), 0.f);
                na.z = fmaxf(fmaf(xv.z, sc.z, sh.z), 0.f);
                na.w = fmaxf(fmaf(xv.w, sc.w, sh.w), 0.f);
            }
            const float4* Wv = (const float4*)(W + kc * D);
            nb0 = Wv[tid]; nb1 = Wv[tid + 256];
        }
#pragma unroll
        for (int k = 0; k < 16; k++) {
            float4 b = *(const float4*)(&Bs[cur][k][tn * 4]);
            float4 a0 = *(const float4*)(&As[cur][k][tm * 8]);
            float4 a1 = *(const float4*)(&As[cur][k][tm * 8 + 4]);
            float av[8] = {a0.x, a0.y, a0.z, a0.w, a1.x, a1.y, a1.z, a1.w};
#pragma unroll
            for (int r = 0; r < 8; r++) {
                acc[r][0] = fmaf(av[r], b.x, acc[r][0]);
                acc[r][1] = fmaf(av[r], b.y, acc[r][1]);
                acc[r][2] = fmaf(av[r], b.z, acc[r][2]);
                acc[r][3] = fmaf(av[r], b.w, acc[r][3]);
            }
        }
        if (kk < 7) {
            const int nxt = cur ^ 1;
            As[nxt][lk + 0][lm] = na.x; As[nxt][lk + 1][lm] = na.y;
            As[nxt][lk + 2][lm] = na.z; As[nxt][lk + 3][lm] = na.w;
            float4* Bv = (float4*)&Bs[nxt][0][0];
            Bv[tid] = nb0; Bv[tid + 256] = nb1;
            __syncthreads();
        }
    }

    float4 bb = *(const float4*)(b2 + (size_t)layer * D + tn * 4);
#pragma unroll
    for (int r = 0; r < 8; r++) {
        int gm = m0 + tm * 8 + r;
        if (gm < NN) {
            float4 v;
            v.x = fmaxf(acc[r][0] + bb.x, 0.f);
            v.y = fmaxf(acc[r][1] + bb.y, 0.f);
            v.z = fmaxf(acc[r][2] + bb.z, 0.f);
            v.w = fmaxf(acc[r][3] + bb.w, 0.f);
            *(float4*)(g_h + (size_t)gm * D + tn * 4) = v;
        }
    }
}

// ---------------- GEMM3 (final): out = h @ Wout + bout ----------------
__global__ void __launch_bounds__(256) gemm3_kernel(const float* __restrict__ Wout,
                                                    const float* __restrict__ bout,
                                                    float* __restrict__ out) {
    __shared__ float Bs[16][64];
    __shared__ float As[16][68];

    int tid = threadIdx.x;
    int tn = tid & 15;
    int tm = tid >> 4;
    int m0 = blockIdx.x * 64;

    float acc[4][4];
#pragma unroll
    for (int r = 0; r < 4; r++)
#pragma unroll
        for (int c = 0; c < 4; c++) acc[r][c] = 0.f;

    int lm = tid >> 2;
    int lk = (tid & 3) * 4;
    int gm_ld = m0 + lm;

    for (int kk = 0; kk < D; kk += 16) {
        {
            const float4* Wv = (const float4*)(Wout + kk * OD);
            float4* Bv = (float4*)&Bs[0][0];
            Bv[tid] = Wv[tid];
        }
        {
            float4 a = make_float4(0.f, 0.f, 0.f, 0.f);
            if (gm_ld < NN) {
                a = *(const float4*)(g_h + (size_t)gm_ld * D + kk + lk);
            }
            As[lk + 0][lm] = a.x;
            As[lk + 1][lm] = a.y;
            As[lk + 2][lm] = a.z;
            As[lk + 3][lm] = a.w;
        }
        __syncthreads();
#pragma unroll
        for (int k = 0; k < 16; k++) {
            float4 b = *(const float4*)(&Bs[k][tn * 4]);
            float4 a = *(const float4*)(&As[k][tm * 4]);
            float av[4] = {a.x, a.y, a.z, a.w};
#pragma unroll
            for (int r = 0; r < 4; r++) {
                acc[r][0] = fmaf(av[r], b.x, acc[r][0]);
                acc[r][1] = fmaf(av[r], b.y, acc[r][1]);
                acc[r][2] = fmaf(av[r], b.z, acc[r][2]);
                acc[r][3] = fmaf(av[r], b.w, acc[r][3]);
            }
        }
        __syncthreads();
    }

    float4 bb = *(const float4*)(bout + tn * 4);
#pragma unroll
    for (int r = 0; r < 4; r++) {
        int gm = m0 + tm * 4 + r;
        if (gm < NN) {
            float4 v;
            v.x = acc[r][0] + bb.x;
            v.y = acc[r][1] + bb.y;
            v.z = acc[r][2] + bb.z;
            v.w = acc[r][3] + bb.w;
            *(float4*)(out + (size_t)gm * OD + tn * 4) = v;
        }
    }
}

// ---------------- launch ----------------
extern "C" void kernel_launch(void* const* d_in, const int* in_sizes, int n_in,
                              void* d_out, int out_size) {
    const float* node_feat = (const float*)d_in[0];
    const int*   src       = (const int*)d_in[1];
    const int*   dst       = (const int*)d_in[2];
    const float* W1        = (const float*)d_in[3];
    const float* b1        = (const float*)d_in[4];
    const float* gamma     = (const float*)d_in[5];
    const float* beta      = (const float*)d_in[6];
    const float* W2        = (const float*)d_in[7];
    const float* b2        = (const float*)d_in[8];
    const float* eps       = (const float*)d_in[9];
    const float* Wout      = (const float*)d_in[10];
    const float* bout      = (const float*)d_in[11];
    float* out = (float*)d_out;

    const int gemm_grid = (NN + 63) / 64;   // 782
    const int edge_grid = NE / 256;         // 6250 (exact)
    const int node_grid = (NN + 255) / 256; // 196
    const int gath_grid = (NN + 7) / 8;     // 6250

    // CSR build (once per call, reused by all 3 layers)
    csr_zero_kernel<<<node_grid, 256>>>();
    csr_hist_kernel<<<edge_grid, 256>>>(dst);
    csr_scan_kernel<<<1, 1024>>>();
    csr_fill_kernel<<<edge_grid, 256>>>(src, dst);

    for (int l = 0; l < NL; l++) {
        gather_kernel<<<gath_grid, 256>>>(node_feat, eps, l);
        gemm1_kernel<<<gemm_grid, 256>>>(W1, b1, l);
        bnfin_kernel<<<1, 128>>>(gamma, beta, l);
        gemm2_kernel<<<gemm_grid, 256>>>(W2, b2, l);
    }
    gemm3_kernel<<<gemm_grid, 256>>>(Wout, bout, out);
}